// round 7
// baseline (speedup 1.0000x reference)
#include <cuda_runtime.h>
#include <math.h>
#include <stdint.h>

#define HIDDEN 4096
#define INTER  16384
#define NTOK   8192
#define EPS    1e-5f

#define SA_STRIDE 36
#define SB_STRIDE 132
#define SA_FLOATS (128 * SA_STRIDE)                 // 4608
#define SB_FLOATS (32 * SB_STRIDE)                  // 4224
#define STAGE_FLOATS (SA_FLOATS + SB_FLOATS)        // 8832
#define SMEM_BYTES (2 * STAGE_FLOATS * 4)           // 70656

// ---------------- scratch (allocation-free) ----------------
__device__ float g_res[(size_t)NTOK * HIDDEN];      // fp32 residual
__device__ float g_ln [(size_t)NTOK * HIDDEN];      // tf32-rounded LN out
__device__ float g_inter[(size_t)NTOK * INTER];     // tf32-rounded gelu out
__device__ float g_w1r[(size_t)HIDDEN * INTER];     // tf32-rounded inter_w  [H][I]
__device__ float g_w2r[(size_t)INTER * HIDDEN];     // tf32-rounded output_w [I][H]

// ---------------- helpers ----------------
__device__ __forceinline__ unsigned f2tf32u(float x) {
    unsigned r;
    asm("cvt.rna.tf32.f32 %0, %1;" : "=r"(r) : "f"(x));
    return r;
}
__device__ __forceinline__ float gelu_tanh(float x) {
    float x3 = x * x * x;
    float t = tanhf(0.7978845608028654f * (x + 0.044715f * x3));
    return 0.5f * x * (1.0f + t);
}
__device__ __forceinline__ uint32_t smem_u32(const void* p) {
    uint32_t a;
    asm("{ .reg .u64 t; cvta.to.shared.u64 t, %1; cvt.u32.u64 %0, t; }" : "=r"(a) : "l"(p));
    return a;
}
#define CPASYNC16(d, s) \
    asm volatile("{ .reg .u64 g; cvta.to.global.u64 g, %1; " \
                 "cp.async.cg.shared.global [%0], [g], 16; }" \
                 :: "r"(d), "l"(s) : "memory")
#define CP_COMMIT() asm volatile("cp.async.commit_group;" ::: "memory")
#define CP_WAIT1()  asm volatile("cp.async.wait_group 1;" ::: "memory")

__device__ __forceinline__ void mma_tf32(float c[4], const unsigned a[4], const unsigned b[2]) {
    asm volatile(
        "mma.sync.aligned.m16n8k8.row.col.f32.tf32.tf32.f32 "
        "{%0,%1,%2,%3}, {%4,%5,%6,%7}, {%8,%9}, {%0,%1,%2,%3};\n"
        : "+f"(c[0]), "+f"(c[1]), "+f"(c[2]), "+f"(c[3])
        : "r"(a[0]), "r"(a[1]), "r"(a[2]), "r"(a[3]),
          "r"(b[0]), "r"(b[1]));
}

// ---------------------------------------------------------------------------
// round-copy: dst = tf32_rna(src), float4 grid-stride
// ---------------------------------------------------------------------------
__global__ __launch_bounds__(256)
void round_copy(const float4* __restrict__ src, float4* __restrict__ dst, size_t n4) {
    size_t i = (size_t)blockIdx.x * 256 + threadIdx.x;
    size_t stride = (size_t)gridDim.x * 256;
    for (; i < n4; i += stride) {
        float4 v = src[i];
        v.x = __uint_as_float(f2tf32u(v.x));
        v.y = __uint_as_float(f2tf32u(v.y));
        v.z = __uint_as_float(f2tf32u(v.z));
        v.w = __uint_as_float(f2tf32u(v.w));
        dst[i] = v;
    }
}

// ---------------------------------------------------------------------------
// Kernel 1: res = input + residual + bias (fp32); ln = tf32(LN(res)*g+b)
// ---------------------------------------------------------------------------
__global__ __launch_bounds__(256)
void fused_add_ln(const float* __restrict__ inp,
                  const float* __restrict__ resd,
                  const float* __restrict__ bias,
                  const float* __restrict__ gamma,
                  const float* __restrict__ beta) {
    int row = blockIdx.x;
    int tid = threadIdx.x;
    const float4* ip = (const float4*)(inp  + (size_t)row * HIDDEN);
    const float4* rp = (const float4*)(resd + (size_t)row * HIDDEN);
    const float4* bp = (const float4*)bias;

    float4 v[4];
    float s = 0.f, ss = 0.f;
#pragma unroll
    for (int i = 0; i < 4; i++) {
        int idx = tid + i * 256;
        float4 a = ip[idx], b = rp[idx], c = bp[idx];
        float4 r;
        r.x = a.x + b.x + c.x; r.y = a.y + b.y + c.y;
        r.z = a.z + b.z + c.z; r.w = a.w + b.w + c.w;
        v[i] = r;
        s  += r.x + r.y + r.z + r.w;
        ss += r.x * r.x + r.y * r.y + r.z * r.z + r.w * r.w;
    }
    float4* ro = (float4*)(g_res + (size_t)row * HIDDEN);
#pragma unroll
    for (int i = 0; i < 4; i++) ro[tid + i * 256] = v[i];

    __shared__ float rs[256], rss[256];
    rs[tid] = s; rss[tid] = ss;
    __syncthreads();
    for (int o = 128; o > 0; o >>= 1) {
        if (tid < o) { rs[tid] += rs[tid + o]; rss[tid] += rss[tid + o]; }
        __syncthreads();
    }
    float mu   = rs[0] * (1.0f / HIDDEN);
    float var  = rss[0] * (1.0f / HIDDEN) - mu * mu;
    float rstd = rsqrtf(var + EPS);

    const float4* gp  = (const float4*)gamma;
    const float4* btp = (const float4*)beta;
    float4* lo = (float4*)(g_ln + (size_t)row * HIDDEN);
#pragma unroll
    for (int i = 0; i < 4; i++) {
        int idx = tid + i * 256;
        float4 g = gp[idx], bt = btp[idx], r = v[i];
        float4 o;
        o.x = __uint_as_float(f2tf32u((r.x - mu) * rstd * g.x + bt.x));
        o.y = __uint_as_float(f2tf32u((r.y - mu) * rstd * g.y + bt.y));
        o.z = __uint_as_float(f2tf32u((r.z - mu) * rstd * g.z + bt.z));
        o.w = __uint_as_float(f2tf32u((r.w - mu) * rstd * g.w + bt.w));
        lo[idx] = o;
    }
}

// ---------------------------------------------------------------------------
// Pipelined tf32 GEMM: C[M,N] = A[M,K] @ B[K,N] (+ epilogue)
// 128x128x32 CTA tile, 8 warps (4Mx2N), warp tile 32x64.
// 2-stage cp.async double buffer, 2 CTAs/SM. Inputs pre-rounded to tf32.
// EPI==0: A=g_ln,    out = tf32(gelu(c + bias)) -> g_inter
// EPI==1: A=g_inter, out = c + g_res + bias -> Cout
// ---------------------------------------------------------------------------
template <int EPI, int K, int N>
__global__ __launch_bounds__(256, 2)
void gemm_tf32(const float* __restrict__ Bw,
               const float* __restrict__ bias,
               float* __restrict__ Cout) {
    extern __shared__ float sm[];
    const float* __restrict__ A = (EPI == 0) ? g_ln : g_inter;

    int tid = threadIdx.x;
    int warp = tid >> 5, lane = tid & 31;
    int wm = warp & 3;
    int wn = warp >> 2;
    int gID = lane >> 2;
    int tg = lane & 3;

    // supertiled rasterization: GROUP_M = 8
    const int num_n = N / 128;
    int pid = blockIdx.x;
    int grp = 8 * num_n;
    int pm = (pid / grp) * 8 + (pid % 8);
    int pn = (pid % grp) / 8;
    size_t m0 = (size_t)pm * 128, n0 = (size_t)pn * 128;

    const int NK = K / 32;

    // ---- stage loader ----
    auto load_tiles = [&](int s, int i) {
        float* dA = sm + s * STAGE_FLOATS;
        float* dB = dA + SA_FLOATS;
        size_t k0 = (size_t)i * 32;
        const float* Ab = A  + m0 * K + k0;
        const float* Bb = Bw + k0 * N + n0;
#pragma unroll
        for (int c = 0; c < 4; c++) {
            int f = tid + c * 256;
            int r = f >> 3, cc = (f & 7) << 2;
            CPASYNC16(smem_u32(dA + r * SA_STRIDE + cc), Ab + (size_t)r * K + cc);
        }
#pragma unroll
        for (int c = 0; c < 4; c++) {
            int f = tid + c * 256;
            int r = f >> 5, cc = (f & 31) << 2;
            CPASYNC16(smem_u32(dB + r * SB_STRIDE + cc), Bb + (size_t)r * N + cc);
        }
    };

    float acc[2][8][4];
#pragma unroll
    for (int mi = 0; mi < 2; mi++)
#pragma unroll
        for (int ni = 0; ni < 8; ni++)
#pragma unroll
            for (int j = 0; j < 4; j++) acc[mi][ni][j] = 0.f;

    // prologue: tiles 0 and 1 in flight
    load_tiles(0, 0); CP_COMMIT();
    load_tiles(1, 1); CP_COMMIT();

#pragma unroll 1
    for (int i = 0; i < NK; i++) {
        CP_WAIT1();
        __syncthreads();
        int s = i & 1;
        const float* cA = sm + s * STAGE_FLOATS;
        const float* cB = cA + SA_FLOATS;

#pragma unroll
        for (int ks = 0; ks < 4; ks++) {
            int kk = ks * 8;
            unsigned a[2][4], b[8][2];
#pragma unroll
            for (int mi = 0; mi < 2; mi++) {
                int base = (wm * 32 + mi * 16 + gID) * SA_STRIDE + kk + tg;
                a[mi][0] = __float_as_uint(cA[base]);
                a[mi][1] = __float_as_uint(cA[base + 8 * SA_STRIDE]);
                a[mi][2] = __float_as_uint(cA[base + 4]);
                a[mi][3] = __float_as_uint(cA[base + 8 * SA_STRIDE + 4]);
            }
#pragma unroll
            for (int ni = 0; ni < 8; ni++) {
                int col = wn * 64 + ni * 8 + gID;
                b[ni][0] = __float_as_uint(cB[(kk + tg) * SB_STRIDE + col]);
                b[ni][1] = __float_as_uint(cB[(kk + tg + 4) * SB_STRIDE + col]);
            }
#pragma unroll
            for (int mi = 0; mi < 2; mi++)
#pragma unroll
                for (int ni = 0; ni < 8; ni++)
                    mma_tf32(acc[mi][ni], a[mi], b[ni]);
        }

        __syncthreads();
        if (i + 2 < NK) load_tiles(s, i + 2);
        CP_COMMIT();
    }

    // ---- epilogue (float2 stores) ----
#pragma unroll
    for (int mi = 0; mi < 2; mi++) {
#pragma unroll
        for (int ni = 0; ni < 8; ni++) {
            size_t row0 = m0 + wm * 32 + mi * 16 + gID;
            size_t col = n0 + wn * 64 + ni * 8 + tg * 2;
            float2 b2 = *(const float2*)(bias + col);
#pragma unroll
            for (int h = 0; h < 2; h++) {
                size_t row = row0 + h * 8;
                float x0 = acc[mi][ni][h * 2 + 0] + b2.x;
                float x1 = acc[mi][ni][h * 2 + 1] + b2.y;
                if (EPI == 0) {
                    float2 o;
                    o.x = __uint_as_float(f2tf32u(gelu_tanh(x0)));
                    o.y = __uint_as_float(f2tf32u(gelu_tanh(x1)));
                    *(float2*)(g_inter + row * INTER + col) = o;
                } else {
                    float2 r2 = *(const float2*)(g_res + row * HIDDEN + col);
                    float2 o;
                    o.x = x0 + r2.x;
                    o.y = x1 + r2.y;
                    *(float2*)(Cout + row * HIDDEN + col) = o;
                }
            }
        }
    }
}

// ---------------------------------------------------------------------------
extern "C" void kernel_launch(void* const* d_in, const int* in_sizes, int n_in,
                              void* d_out, int out_size) {
    const float* input    = (const float*)d_in[0];
    const float* residual = (const float*)d_in[1];
    const float* bias     = (const float*)d_in[3];
    const float* attn_nw  = (const float*)d_in[4];
    const float* attn_nb  = (const float*)d_in[5];
    const float* inter_w  = (const float*)d_in[6];
    const float* inter_b  = (const float*)d_in[7];
    const float* output_w = (const float*)d_in[8];
    const float* output_b = (const float*)d_in[9];
    float* out = (float*)d_out;

    static int attr_done = 0;
    if (!attr_done) {
        cudaFuncSetAttribute(gemm_tf32<0, HIDDEN, INTER>,
                             cudaFuncAttributeMaxDynamicSharedMemorySize, SMEM_BYTES);
        cudaFuncSetAttribute(gemm_tf32<1, INTER, HIDDEN>,
                             cudaFuncAttributeMaxDynamicSharedMemorySize, SMEM_BYTES);
        attr_done = 1;
    }

    fused_add_ln<<<NTOK, 256>>>(input, residual, bias, attn_nw, attn_nb);

    // pre-round weights to tf32 (removes cvt from GEMM mainloops, enables cp.async)
    {
        size_t n4 = (size_t)HIDDEN * INTER / 4;
        round_copy<<<2048, 256>>>((const float4*)inter_w,  (float4*)g_w1r, n4);
        round_copy<<<2048, 256>>>((const float4*)output_w, (float4*)g_w2r, n4);
    }

    // GEMM1: [8192,4096] @ [4096,16384] -> gelu -> g_inter (tf32-rounded)
    gemm_tf32<0, HIDDEN, INTER><<<(NTOK / 128) * (INTER / 128), 256, SMEM_BYTES>>>(
        g_w1r, inter_b, nullptr);
    // GEMM2: [8192,16384] @ [16384,4096] + res + output_b -> out
    gemm_tf32<1, INTER, HIDDEN><<<(NTOK / 128) * (HIDDEN / 128), 256, SMEM_BYTES>>>(
        g_w2r, output_b, out);
}

// round 8
// speedup vs baseline: 2.7533x; 2.7533x over previous
#include <cuda_runtime.h>
#include <cuda_fp16.h>
#include <math.h>
#include <stdint.h>

#define HIDDEN 4096
#define INTER  16384
#define NTOK   8192
#define EPS    1e-5f
#define SSTRIDE 72   // half stride per smem row (64 + 8 pad)

// ---------------- scratch (allocation-free) ----------------
__device__ float  g_res[(size_t)NTOK * HIDDEN];      // fp32 residual
__device__ __half g_lnh[(size_t)NTOK * HIDDEN];      // fp16 LN out
__device__ __half g_interh[(size_t)NTOK * INTER];    // fp16 gelu out
__device__ __half g_w1h[(size_t)INTER * HIDDEN];     // fp16 inter_w^T  [I][H]
__device__ __half g_w2h[(size_t)HIDDEN * INTER];     // fp16 output_w^T [H][I]

// ---------------- helpers ----------------
__device__ __forceinline__ float gelu_tanh(float x) {
    float x3 = x * x * x;
    float t = tanhf(0.7978845608028654f * (x + 0.044715f * x3));
    return 0.5f * x * (1.0f + t);
}

__device__ __forceinline__ void mma_f16(float c[4], const uint32_t a[4], const uint32_t b[2]) {
    asm volatile(
        "mma.sync.aligned.m16n8k16.row.col.f32.f16.f16.f32 "
        "{%0,%1,%2,%3}, {%4,%5,%6,%7}, {%8,%9}, {%0,%1,%2,%3};\n"
        : "+f"(c[0]), "+f"(c[1]), "+f"(c[2]), "+f"(c[3])
        : "r"(a[0]), "r"(a[1]), "r"(a[2]), "r"(a[3]),
          "r"(b[0]), "r"(b[1]));
}

// ---------------------------------------------------------------------------
// Kernel 1: res = input + residual + bias (fp32); lnh = fp16(LN(res)*g+b)
// ---------------------------------------------------------------------------
__global__ __launch_bounds__(256)
void fused_add_ln(const float* __restrict__ inp,
                  const float* __restrict__ resd,
                  const float* __restrict__ bias,
                  const float* __restrict__ gamma,
                  const float* __restrict__ beta) {
    int row = blockIdx.x;
    int tid = threadIdx.x;
    const float4* ip = (const float4*)(inp  + (size_t)row * HIDDEN);
    const float4* rp = (const float4*)(resd + (size_t)row * HIDDEN);
    const float4* bp = (const float4*)bias;

    float4 v[4];
    float s = 0.f, ss = 0.f;
#pragma unroll
    for (int i = 0; i < 4; i++) {
        int idx = tid + i * 256;
        float4 a = ip[idx], b = rp[idx], c = bp[idx];
        float4 r;
        r.x = a.x + b.x + c.x; r.y = a.y + b.y + c.y;
        r.z = a.z + b.z + c.z; r.w = a.w + b.w + c.w;
        v[i] = r;
        s  += r.x + r.y + r.z + r.w;
        ss += r.x * r.x + r.y * r.y + r.z * r.z + r.w * r.w;
    }
    float4* ro = (float4*)(g_res + (size_t)row * HIDDEN);
#pragma unroll
    for (int i = 0; i < 4; i++) ro[tid + i * 256] = v[i];

    __shared__ float rs[256], rss[256];
    rs[tid] = s; rss[tid] = ss;
    __syncthreads();
    for (int o = 128; o > 0; o >>= 1) {
        if (tid < o) { rs[tid] += rs[tid + o]; rss[tid] += rss[tid + o]; }
        __syncthreads();
    }
    float mu   = rs[0] * (1.0f / HIDDEN);
    float var  = rss[0] * (1.0f / HIDDEN) - mu * mu;
    float rstd = rsqrtf(var + EPS);

    const float4* gp  = (const float4*)gamma;
    const float4* btp = (const float4*)beta;
    __half2* lo = (__half2*)(g_lnh + (size_t)row * HIDDEN);
#pragma unroll
    for (int i = 0; i < 4; i++) {
        int idx = tid + i * 256;
        float4 g = gp[idx], bt = btp[idx], r = v[i];
        float o0 = (r.x - mu) * rstd * g.x + bt.x;
        float o1 = (r.y - mu) * rstd * g.y + bt.y;
        float o2 = (r.z - mu) * rstd * g.z + bt.z;
        float o3 = (r.w - mu) * rstd * g.w + bt.w;
        lo[idx * 2 + 0] = __floats2half2_rn(o0, o1);
        lo[idx * 2 + 1] = __floats2half2_rn(o2, o3);
    }
}

// ---------------------------------------------------------------------------
// Transpose src fp32 [R][C] -> dst fp16 [C][R]
// ---------------------------------------------------------------------------
__global__ __launch_bounds__(256)
void transpose_h(const float* __restrict__ src, __half* __restrict__ dst,
                 int R, int C) {
    __shared__ float t[32][33];
    int tx = threadIdx.x, ty = threadIdx.y;           // 32 x 8
    int bx = blockIdx.x * 32;                          // C offset
    int by = blockIdx.y * 32;                          // R offset
#pragma unroll
    for (int j = 0; j < 32; j += 8)
        t[ty + j][tx] = src[(size_t)(by + ty + j) * C + bx + tx];
    __syncthreads();
#pragma unroll
    for (int j = 0; j < 32; j += 8)
        dst[(size_t)(bx + ty + j) * R + by + tx] = __float2half_rn(t[tx][ty + j]);
}

// ---------------------------------------------------------------------------
// fp16 GEMM: C[M,N] = A[M,K] @ B[N,K]^T (+ epilogue), fp32 accum.
// Block tile 128x128x64, 8 warps (4Mx2N), warp tile 32x64, m16n8k16.
// Synchronous LDG->STS loop (proven structure), 2 CTAs/SM, zero cvt in loop.
// EPI==0: A=g_lnh,    out = fp16(gelu(c + bias)) -> g_interh
// EPI==1: A=g_interh, out = c + g_res + bias -> Cout (fp32)
// ---------------------------------------------------------------------------
template <int EPI, int K, int N>
__global__ __launch_bounds__(256, 2)
void gemm_f16(const __half* __restrict__ Bw,
              const float* __restrict__ bias,
              float* __restrict__ Cout) {
    __shared__ __half sA[128 * SSTRIDE];
    __shared__ __half sB[128 * SSTRIDE];
    const __half* __restrict__ A = (EPI == 0) ? g_lnh : g_interh;

    int tid = threadIdx.x;
    int warp = tid >> 5, lane = tid & 31;
    int wm = warp & 3;       // M slab 0..3
    int wn = warp >> 2;      // N slab 0..1
    int gID = lane >> 2;     // 0..7
    int tg = lane & 3;       // 0..3

    size_t m0 = (size_t)blockIdx.y * 128;
    size_t n0 = (size_t)blockIdx.x * 128;

    float acc[2][8][4];
#pragma unroll
    for (int mi = 0; mi < 2; mi++)
#pragma unroll
        for (int ni = 0; ni < 8; ni++)
#pragma unroll
            for (int j = 0; j < 4; j++) acc[mi][ni][j] = 0.f;

    const int NK = K / 64;
#pragma unroll 1
    for (int i = 0; i < NK; i++) {
        size_t k0 = (size_t)i * 64;
        // load 128x64 halves for A and B (uint4 = 8 halves per chunk)
        uint4 va[4], vb[4];
#pragma unroll
        for (int c = 0; c < 4; c++) {
            int idx = tid + c * 256;
            int r = idx >> 3, c8 = (idx & 7) * 8;
            va[c] = *(const uint4*)(A  + (m0 + r) * K + k0 + c8);
            vb[c] = *(const uint4*)(Bw + (n0 + r) * K + k0 + c8);
        }
#pragma unroll
        for (int c = 0; c < 4; c++) {
            int idx = tid + c * 256;
            int r = idx >> 3, c8 = (idx & 7) * 8;
            *(uint4*)(sA + r * SSTRIDE + c8) = va[c];
            *(uint4*)(sB + r * SSTRIDE + c8) = vb[c];
        }
        __syncthreads();

#pragma unroll
        for (int ks = 0; ks < 4; ks++) {
            int kk = ks * 16;
            uint32_t a[2][4], b[8][2];
#pragma unroll
            for (int mi = 0; mi < 2; mi++) {
                int row = wm * 32 + mi * 16 + gID;
                a[mi][0] = *(const uint32_t*)(sA + row * SSTRIDE + kk + tg * 2);
                a[mi][1] = *(const uint32_t*)(sA + (row + 8) * SSTRIDE + kk + tg * 2);
                a[mi][2] = *(const uint32_t*)(sA + row * SSTRIDE + kk + 8 + tg * 2);
                a[mi][3] = *(const uint32_t*)(sA + (row + 8) * SSTRIDE + kk + 8 + tg * 2);
            }
#pragma unroll
            for (int ni = 0; ni < 8; ni++) {
                int col = wn * 64 + ni * 8 + gID;
                b[ni][0] = *(const uint32_t*)(sB + col * SSTRIDE + kk + tg * 2);
                b[ni][1] = *(const uint32_t*)(sB + col * SSTRIDE + kk + 8 + tg * 2);
            }
#pragma unroll
            for (int mi = 0; mi < 2; mi++)
#pragma unroll
                for (int ni = 0; ni < 8; ni++)
                    mma_f16(acc[mi][ni], a[mi], b[ni]);
        }
        __syncthreads();
    }

    // ---- epilogue ----
#pragma unroll
    for (int mi = 0; mi < 2; mi++) {
#pragma unroll
        for (int ni = 0; ni < 8; ni++) {
            size_t row0 = m0 + wm * 32 + mi * 16 + gID;
            size_t col = n0 + wn * 64 + ni * 8 + tg * 2;
            float2 b2 = *(const float2*)(bias + col);
#pragma unroll
            for (int h = 0; h < 2; h++) {
                size_t row = row0 + h * 8;
                float x0 = acc[mi][ni][h * 2 + 0] + b2.x;
                float x1 = acc[mi][ni][h * 2 + 1] + b2.y;
                if (EPI == 0) {
                    *(__half2*)(g_interh + row * INTER + col) =
                        __floats2half2_rn(gelu_tanh(x0), gelu_tanh(x1));
                } else {
                    float2 r2 = *(const float2*)(g_res + row * HIDDEN + col);
                    float2 o;
                    o.x = x0 + r2.x;
                    o.y = x1 + r2.y;
                    *(float2*)(Cout + row * HIDDEN + col) = o;
                }
            }
        }
    }
}

// ---------------------------------------------------------------------------
extern "C" void kernel_launch(void* const* d_in, const int* in_sizes, int n_in,
                              void* d_out, int out_size) {
    const float* input    = (const float*)d_in[0];
    const float* residual = (const float*)d_in[1];
    const float* bias     = (const float*)d_in[3];
    const float* attn_nw  = (const float*)d_in[4];
    const float* attn_nb  = (const float*)d_in[5];
    const float* inter_w  = (const float*)d_in[6];
    const float* inter_b  = (const float*)d_in[7];
    const float* output_w = (const float*)d_in[8];
    const float* output_b = (const float*)d_in[9];
    float* out = (float*)d_out;

    fused_add_ln<<<NTOK, 256>>>(input, residual, bias, attn_nw, attn_nb);

    // weight transposes -> fp16 [N][K] operands
    transpose_h<<<dim3(INTER / 32, HIDDEN / 32), dim3(32, 8)>>>(inter_w, g_w1h, HIDDEN, INTER);
    transpose_h<<<dim3(HIDDEN / 32, INTER / 32), dim3(32, 8)>>>(output_w, g_w2h, INTER, HIDDEN);

    // GEMM1: [8192,4096] @ [4096,16384] -> gelu -> g_interh
    gemm_f16<0, HIDDEN, INTER><<<dim3(INTER / 128, NTOK / 128), 256>>>(
        g_w1h, inter_b, nullptr);
    // GEMM2: [8192,16384] @ [16384,4096] + res + output_b -> out
    gemm_f16<1, INTER, HIDDEN><<<dim3(HIDDEN / 128, NTOK / 128), 256>>>(
        g_w2h, output_b, out);
}

// round 9
// speedup vs baseline: 2.7607x; 1.0027x over previous
#include <cuda_runtime.h>
#include <cuda_fp16.h>
#include <math.h>
#include <stdint.h>

#define HIDDEN 4096
#define INTER  16384
#define NTOK   8192
#define EPS    1e-5f
#define SSTRIDE 72   // half stride per smem row (64 + 8 pad)

// ---------------- scratch (allocation-free) ----------------
__device__ float  g_res[(size_t)NTOK * HIDDEN];      // fp32 residual
__device__ __half g_lnh[(size_t)NTOK * HIDDEN];      // fp16 LN out
__device__ __half g_interh[(size_t)NTOK * INTER];    // fp16 gelu out
__device__ __half g_w1h[(size_t)INTER * HIDDEN];     // fp16 inter_w^T  [I][H]
__device__ __half g_w2h[(size_t)HIDDEN * INTER];     // fp16 output_w^T [H][I]

// ---------------- helpers ----------------
__device__ __forceinline__ float gelu_tanh(float x) {
    float x3 = x * x * x;
    float t = tanhf(0.7978845608028654f * (x + 0.044715f * x3));
    return 0.5f * x * (1.0f + t);
}

__device__ __forceinline__ void mma_f16(float c[4], const uint32_t a[4], const uint32_t b[2]) {
    asm volatile(
        "mma.sync.aligned.m16n8k16.row.col.f32.f16.f16.f32 "
        "{%0,%1,%2,%3}, {%4,%5,%6,%7}, {%8,%9}, {%0,%1,%2,%3};\n"
        : "+f"(c[0]), "+f"(c[1]), "+f"(c[2]), "+f"(c[3])
        : "r"(a[0]), "r"(a[1]), "r"(a[2]), "r"(a[3]),
          "r"(b[0]), "r"(b[1]));
}

// ---------------------------------------------------------------------------
// Kernel 1: res = input + residual + bias (fp32); lnh = fp16(LN(res)*g+b)
// ---------------------------------------------------------------------------
__global__ __launch_bounds__(256)
void fused_add_ln(const float* __restrict__ inp,
                  const float* __restrict__ resd,
                  const float* __restrict__ bias,
                  const float* __restrict__ gamma,
                  const float* __restrict__ beta) {
    int row = blockIdx.x;
    int tid = threadIdx.x;
    const float4* ip = (const float4*)(inp  + (size_t)row * HIDDEN);
    const float4* rp = (const float4*)(resd + (size_t)row * HIDDEN);
    const float4* bp = (const float4*)bias;

    float4 v[4];
    float s = 0.f, ss = 0.f;
#pragma unroll
    for (int i = 0; i < 4; i++) {
        int idx = tid + i * 256;
        float4 a = ip[idx], b = rp[idx], c = bp[idx];
        float4 r;
        r.x = a.x + b.x + c.x; r.y = a.y + b.y + c.y;
        r.z = a.z + b.z + c.z; r.w = a.w + b.w + c.w;
        v[i] = r;
        s  += r.x + r.y + r.z + r.w;
        ss += r.x * r.x + r.y * r.y + r.z * r.z + r.w * r.w;
    }
    float4* ro = (float4*)(g_res + (size_t)row * HIDDEN);
#pragma unroll
    for (int i = 0; i < 4; i++) ro[tid + i * 256] = v[i];

    __shared__ float rs[256], rss[256];
    rs[tid] = s; rss[tid] = ss;
    __syncthreads();
    for (int o = 128; o > 0; o >>= 1) {
        if (tid < o) { rs[tid] += rs[tid + o]; rss[tid] += rss[tid + o]; }
        __syncthreads();
    }
    float mu   = rs[0] * (1.0f / HIDDEN);
    float var  = rss[0] * (1.0f / HIDDEN) - mu * mu;
    float rstd = rsqrtf(var + EPS);

    const float4* gp  = (const float4*)gamma;
    const float4* btp = (const float4*)beta;
    __half2* lo = (__half2*)(g_lnh + (size_t)row * HIDDEN);
#pragma unroll
    for (int i = 0; i < 4; i++) {
        int idx = tid + i * 256;
        float4 g = gp[idx], bt = btp[idx], r = v[i];
        float o0 = (r.x - mu) * rstd * g.x + bt.x;
        float o1 = (r.y - mu) * rstd * g.y + bt.y;
        float o2 = (r.z - mu) * rstd * g.z + bt.z;
        float o3 = (r.w - mu) * rstd * g.w + bt.w;
        lo[idx * 2 + 0] = __floats2half2_rn(o0, o1);
        lo[idx * 2 + 1] = __floats2half2_rn(o2, o3);
    }
}

// ---------------------------------------------------------------------------
// Transpose src fp32 [R][C] -> dst fp16 [C][R]
// ---------------------------------------------------------------------------
__global__ __launch_bounds__(256)
void transpose_h(const float* __restrict__ src, __half* __restrict__ dst,
                 int R, int C) {
    __shared__ float t[32][33];
    int tx = threadIdx.x, ty = threadIdx.y;           // 32 x 8
    int bx = blockIdx.x * 32;                          // C offset
    int by = blockIdx.y * 32;                          // R offset
#pragma unroll
    for (int j = 0; j < 32; j += 8)
        t[ty + j][tx] = src[(size_t)(by + ty + j) * C + bx + tx];
    __syncthreads();
#pragma unroll
    for (int j = 0; j < 32; j += 8)
        dst[(size_t)(bx + ty + j) * R + by + tx] = __float2half_rn(t[tx][ty + j]);
}

// ---------------------------------------------------------------------------
// fp16 GEMM: C[M,N] = A[M,K] @ B[N,K]^T (+ epilogue), fp32 accum.
// Block tile 128x128x64, 8 warps (4Mx2N), warp tile 32x64, m16n8k16.
// Synchronous loop with IMMEDIATE LDG->STS (no register staging -> no spills).
// EPI==0: A=g_lnh,    out = fp16(gelu(c + bias)) -> g_interh
// EPI==1: A=g_interh, out = c + g_res + bias -> Cout (fp32)
// ---------------------------------------------------------------------------
template <int EPI, int K, int N>
__global__ __launch_bounds__(256, 2)
void gemm_f16(const __half* __restrict__ Bw,
              const float* __restrict__ bias,
              float* __restrict__ Cout) {
    __shared__ __half sA[128 * SSTRIDE];
    __shared__ __half sB[128 * SSTRIDE];
    const __half* __restrict__ A = (EPI == 0) ? g_lnh : g_interh;

    int tid = threadIdx.x;
    int warp = tid >> 5, lane = tid & 31;
    int wm = warp & 3;       // M slab 0..3
    int wn = warp >> 2;      // N slab 0..1
    int gID = lane >> 2;     // 0..7
    int tg = lane & 3;       // 0..3

    size_t m0 = (size_t)blockIdx.y * 128;
    size_t n0 = (size_t)blockIdx.x * 128;

    // per-thread fixed load coordinates: row pair, 16B column chunk
    int lr = tid >> 3;              // 0..31 (row within 32-row slab)
    int lc = (tid & 7) * 8;         // half offset 0..56

    float acc[2][8][4];
#pragma unroll
    for (int mi = 0; mi < 2; mi++)
#pragma unroll
        for (int ni = 0; ni < 8; ni++)
#pragma unroll
            for (int j = 0; j < 4; j++) acc[mi][ni][j] = 0.f;

    const int NK = K / 64;
#pragma unroll 1
    for (int i = 0; i < NK; i++) {
        size_t k0 = (size_t)i * 64;
        // 128x64 halves each for A and B; immediate LDG->STS, one live temp
#pragma unroll
        for (int c = 0; c < 4; c++) {
            int r = lr + c * 32;
            uint4 t = *(const uint4*)(A + (m0 + r) * K + k0 + lc);
            *(uint4*)(sA + r * SSTRIDE + lc) = t;
        }
#pragma unroll
        for (int c = 0; c < 4; c++) {
            int r = lr + c * 32;
            uint4 t = *(const uint4*)(Bw + (n0 + r) * K + k0 + lc);
            *(uint4*)(sB + r * SSTRIDE + lc) = t;
        }
        __syncthreads();

#pragma unroll
        for (int ks = 0; ks < 4; ks++) {
            int kk = ks * 16;
            uint32_t a[2][4], b[8][2];
#pragma unroll
            for (int mi = 0; mi < 2; mi++) {
                int row = wm * 32 + mi * 16 + gID;
                a[mi][0] = *(const uint32_t*)(sA + row * SSTRIDE + kk + tg * 2);
                a[mi][1] = *(const uint32_t*)(sA + (row + 8) * SSTRIDE + kk + tg * 2);
                a[mi][2] = *(const uint32_t*)(sA + row * SSTRIDE + kk + 8 + tg * 2);
                a[mi][3] = *(const uint32_t*)(sA + (row + 8) * SSTRIDE + kk + 8 + tg * 2);
            }
#pragma unroll
            for (int ni = 0; ni < 8; ni++) {
                int col = wn * 64 + ni * 8 + gID;
                b[ni][0] = *(const uint32_t*)(sB + col * SSTRIDE + kk + tg * 2);
                b[ni][1] = *(const uint32_t*)(sB + col * SSTRIDE + kk + 8 + tg * 2);
            }
#pragma unroll
            for (int mi = 0; mi < 2; mi++)
#pragma unroll
                for (int ni = 0; ni < 8; ni++)
                    mma_f16(acc[mi][ni], a[mi], b[ni]);
        }
        __syncthreads();
    }

    // ---- epilogue ----
#pragma unroll
    for (int mi = 0; mi < 2; mi++) {
#pragma unroll
        for (int ni = 0; ni < 8; ni++) {
            size_t row0 = m0 + wm * 32 + mi * 16 + gID;
            size_t col = n0 + wn * 64 + ni * 8 + tg * 2;
            float2 b2 = *(const float2*)(bias + col);
#pragma unroll
            for (int h = 0; h < 2; h++) {
                size_t row = row0 + h * 8;
                float x0 = acc[mi][ni][h * 2 + 0] + b2.x;
                float x1 = acc[mi][ni][h * 2 + 1] + b2.y;
                if (EPI == 0) {
                    *(__half2*)(g_interh + row * INTER + col) =
                        __floats2half2_rn(gelu_tanh(x0), gelu_tanh(x1));
                } else {
                    float2 r2 = *(const float2*)(g_res + row * HIDDEN + col);
                    float2 o;
                    o.x = x0 + r2.x;
                    o.y = x1 + r2.y;
                    *(float2*)(Cout + row * HIDDEN + col) = o;
                }
            }
        }
    }
}

// ---------------------------------------------------------------------------
extern "C" void kernel_launch(void* const* d_in, const int* in_sizes, int n_in,
                              void* d_out, int out_size) {
    const float* input    = (const float*)d_in[0];
    const float* residual = (const float*)d_in[1];
    const float* bias     = (const float*)d_in[3];
    const float* attn_nw  = (const float*)d_in[4];
    const float* attn_nb  = (const float*)d_in[5];
    const float* inter_w  = (const float*)d_in[6];
    const float* inter_b  = (const float*)d_in[7];
    const float* output_w = (const float*)d_in[8];
    const float* output_b = (const float*)d_in[9];
    float* out = (float*)d_out;

    fused_add_ln<<<NTOK, 256>>>(input, residual, bias, attn_nw, attn_nb);

    // weight transposes -> fp16 [N][K] operands
    transpose_h<<<dim3(INTER / 32, HIDDEN / 32), dim3(32, 8)>>>(inter_w, g_w1h, HIDDEN, INTER);
    transpose_h<<<dim3(HIDDEN / 32, INTER / 32), dim3(32, 8)>>>(output_w, g_w2h, INTER, HIDDEN);

    // GEMM1: [8192,4096] @ [4096,16384] -> gelu -> g_interh
    gemm_f16<0, HIDDEN, INTER><<<dim3(INTER / 128, NTOK / 128), 256>>>(
        g_w1h, inter_b, nullptr);
    // GEMM2: [8192,16384] @ [16384,4096] + res + output_b -> out
    gemm_f16<1, INTER, HIDDEN><<<dim3(HIDDEN / 128, NTOK / 128), 256>>>(
        g_w2h, output_b, out);
}

// round 10
// speedup vs baseline: 20.2388x; 7.3310x over previous
#include <cuda_runtime.h>
#include <cuda_fp16.h>
#include <math.h>
#include <stdint.h>

#define HIDDEN 4096
#define INTER  16384
#define NTOK   8192
#define EPS    1e-5f

#define SA_STRIDE 36
#define SB_STRIDE 132

// ---------------- scratch (allocation-free) ----------------
__device__ float g_res[(size_t)NTOK * HIDDEN];      // fp32 residual
__device__ float g_ln [(size_t)NTOK * HIDDEN];      // fp32 LN out
__device__ float g_inter[(size_t)NTOK * INTER];     // fp32 gelu out

// ---------------- helpers ----------------
__device__ __forceinline__ float gelu_tanh(float x) {
    float x3 = x * x * x;
    float t = tanhf(0.7978845608028654f * (x + 0.044715f * x3));
    return 0.5f * x * (1.0f + t);
}

__device__ __forceinline__ uint32_t packh2(float lo, float hi) {
    __half2 h = __floats2half2_rn(lo, hi);   // lo -> low half (even k)
    return *(uint32_t*)&h;
}

__device__ __forceinline__ void mma_f16(float c[4], const uint32_t a[4], const uint32_t b[2]) {
    asm volatile(
        "mma.sync.aligned.m16n8k16.row.col.f32.f16.f16.f32 "
        "{%0,%1,%2,%3}, {%4,%5,%6,%7}, {%8,%9}, {%0,%1,%2,%3};\n"
        : "+f"(c[0]), "+f"(c[1]), "+f"(c[2]), "+f"(c[3])
        : "r"(a[0]), "r"(a[1]), "r"(a[2]), "r"(a[3]),
          "r"(b[0]), "r"(b[1]));
}

// ---------------------------------------------------------------------------
// Kernel 1: res = input + residual + bias (fp32); ln = LN(res)*g+b (fp32)
// ---------------------------------------------------------------------------
__global__ __launch_bounds__(256)
void fused_add_ln(const float* __restrict__ inp,
                  const float* __restrict__ resd,
                  const float* __restrict__ bias,
                  const float* __restrict__ gamma,
                  const float* __restrict__ beta) {
    int row = blockIdx.x;
    int tid = threadIdx.x;
    const float4* ip = (const float4*)(inp  + (size_t)row * HIDDEN);
    const float4* rp = (const float4*)(resd + (size_t)row * HIDDEN);
    const float4* bp = (const float4*)bias;

    float4 v[4];
    float s = 0.f, ss = 0.f;
#pragma unroll
    for (int i = 0; i < 4; i++) {
        int idx = tid + i * 256;
        float4 a = ip[idx], b = rp[idx], c = bp[idx];
        float4 r;
        r.x = a.x + b.x + c.x; r.y = a.y + b.y + c.y;
        r.z = a.z + b.z + c.z; r.w = a.w + b.w + c.w;
        v[i] = r;
        s  += r.x + r.y + r.z + r.w;
        ss += r.x * r.x + r.y * r.y + r.z * r.z + r.w * r.w;
    }
    float4* ro = (float4*)(g_res + (size_t)row * HIDDEN);
#pragma unroll
    for (int i = 0; i < 4; i++) ro[tid + i * 256] = v[i];

    __shared__ float rs[256], rss[256];
    rs[tid] = s; rss[tid] = ss;
    __syncthreads();
    for (int o = 128; o > 0; o >>= 1) {
        if (tid < o) { rs[tid] += rs[tid + o]; rss[tid] += rss[tid + o]; }
        __syncthreads();
    }
    float mu   = rs[0] * (1.0f / HIDDEN);
    float var  = rss[0] * (1.0f / HIDDEN) - mu * mu;
    float rstd = rsqrtf(var + EPS);

    const float4* gp  = (const float4*)gamma;
    const float4* btp = (const float4*)beta;
    float4* lo = (float4*)(g_ln + (size_t)row * HIDDEN);
#pragma unroll
    for (int i = 0; i < 4; i++) {
        int idx = tid + i * 256;
        float4 g = gp[idx], bt = btp[idx], r = v[i];
        float4 o;
        o.x = (r.x - mu) * rstd * g.x + bt.x;
        o.y = (r.y - mu) * rstd * g.y + bt.y;
        o.z = (r.z - mu) * rstd * g.z + bt.z;
        o.w = (r.w - mu) * rstd * g.w + bt.w;
        lo[idx] = o;
    }
}

// ---------------------------------------------------------------------------
// fp16 GEMM on R1's exact memory skeleton:
// C[M,N] = A[M,K] @ B[K,N] (+ epilogue), fp32 accum.
// Block tile 128x128x32, 8 warps (4Mx2N), warp tile 32x64.
// SMEM holds fp32 (R1 layouts); fragments cvt fp32->half2 in registers;
// MMA = m16n8k16.f16 (2 k-steps per tile).
// EPI==0: A=g_ln,    out = gelu(c + bias) -> g_inter (fp32)
// EPI==1: A=g_inter, out = c + g_res + bias -> Cout (fp32)
// ---------------------------------------------------------------------------
template <int EPI, int K, int N>
__global__ __launch_bounds__(256, 2)
void gemm_f16(const float* __restrict__ Bw,
              const float* __restrict__ bias,
              float* __restrict__ Cout) {
    __shared__ float sA[128 * SA_STRIDE];
    __shared__ float sB[32 * SB_STRIDE];
    const float* __restrict__ A = (EPI == 0) ? g_ln : g_inter;

    int tid = threadIdx.x;
    int warp = tid >> 5, lane = tid & 31;
    int wm = warp & 3;       // M slab 0..3
    int wn = warp >> 2;      // N slab 0..1
    int gID = lane >> 2;     // 0..7
    int tg = lane & 3;       // 0..3

    size_t m0 = (size_t)blockIdx.y * 128;
    size_t n0 = (size_t)blockIdx.x * 128;

    float acc[2][8][4];
#pragma unroll
    for (int mi = 0; mi < 2; mi++)
#pragma unroll
        for (int ni = 0; ni < 8; ni++)
#pragma unroll
            for (int j = 0; j < 4; j++) acc[mi][ni][j] = 0.f;

    const int NK = K / 32;
#pragma unroll 1
    for (int i = 0; i < NK; i++) {
        size_t k0 = (size_t)i * 32;
        // A tile: 128 x 32 fp32 (R1 addresses, straight float4 copy)
#pragma unroll
        for (int c = 0; c < 4; c++) {
            int f = tid + c * 256;
            int r = f >> 3, cc = (f & 7) << 2;
            *(float4*)(sA + r * SA_STRIDE + cc) =
                *(const float4*)(A + (m0 + r) * K + k0 + cc);
        }
        // B tile: 32 x 128 fp32 (R1 addresses)
#pragma unroll
        for (int c = 0; c < 4; c++) {
            int f = tid + c * 256;
            int r = f >> 5, cc = (f & 31) << 2;
            *(float4*)(sB + r * SB_STRIDE + cc) =
                *(const float4*)(Bw + (k0 + r) * N + n0 + cc);
        }
        __syncthreads();

#pragma unroll
        for (int ks = 0; ks < 2; ks++) {
            int kk = ks * 16;
            uint32_t a[2][4], b[8][2];
#pragma unroll
            for (int mi = 0; mi < 2; mi++) {
                int row = wm * 32 + mi * 16 + gID;
                float2 f0 = *(const float2*)(sA + row * SA_STRIDE + kk + tg * 2);
                float2 f1 = *(const float2*)(sA + (row + 8) * SA_STRIDE + kk + tg * 2);
                float2 f2 = *(const float2*)(sA + row * SA_STRIDE + kk + 8 + tg * 2);
                float2 f3 = *(const float2*)(sA + (row + 8) * SA_STRIDE + kk + 8 + tg * 2);
                a[mi][0] = packh2(f0.x, f0.y);
                a[mi][1] = packh2(f1.x, f1.y);
                a[mi][2] = packh2(f2.x, f2.y);
                a[mi][3] = packh2(f3.x, f3.y);
            }
#pragma unroll
            for (int ni = 0; ni < 8; ni++) {
                int col = wn * 64 + ni * 8 + gID;
                b[ni][0] = packh2(sB[(kk + 2 * tg) * SB_STRIDE + col],
                                  sB[(kk + 2 * tg + 1) * SB_STRIDE + col]);
                b[ni][1] = packh2(sB[(kk + 2 * tg + 8) * SB_STRIDE + col],
                                  sB[(kk + 2 * tg + 9) * SB_STRIDE + col]);
            }
#pragma unroll
            for (int mi = 0; mi < 2; mi++)
#pragma unroll
                for (int ni = 0; ni < 8; ni++)
                    mma_f16(acc[mi][ni], a[mi], b[ni]);
        }
        __syncthreads();
    }

    // ---- epilogue (R1-identical structure, float2 stores) ----
#pragma unroll
    for (int mi = 0; mi < 2; mi++) {
#pragma unroll
        for (int ni = 0; ni < 8; ni++) {
            size_t row0 = m0 + wm * 32 + mi * 16 + gID;
            size_t col = n0 + wn * 64 + ni * 8 + tg * 2;
            float2 b2 = *(const float2*)(bias + col);
#pragma unroll
            for (int h = 0; h < 2; h++) {
                size_t row = row0 + h * 8;
                float x0 = acc[mi][ni][h * 2 + 0] + b2.x;
                float x1 = acc[mi][ni][h * 2 + 1] + b2.y;
                if (EPI == 0) {
                    float2 o;
                    o.x = gelu_tanh(x0);
                    o.y = gelu_tanh(x1);
                    *(float2*)(g_inter + row * INTER + col) = o;
                } else {
                    float2 r2 = *(const float2*)(g_res + row * HIDDEN + col);
                    float2 o;
                    o.x = x0 + r2.x;
                    o.y = x1 + r2.y;
                    *(float2*)(Cout + row * HIDDEN + col) = o;
                }
            }
        }
    }
}

// ---------------------------------------------------------------------------
extern "C" void kernel_launch(void* const* d_in, const int* in_sizes, int n_in,
                              void* d_out, int out_size) {
    const float* input    = (const float*)d_in[0];
    const float* residual = (const float*)d_in[1];
    const float* bias     = (const float*)d_in[3];
    const float* attn_nw  = (const float*)d_in[4];
    const float* attn_nb  = (const float*)d_in[5];
    const float* inter_w  = (const float*)d_in[6];
    const float* inter_b  = (const float*)d_in[7];
    const float* output_w = (const float*)d_in[8];
    const float* output_b = (const float*)d_in[9];
    float* out = (float*)d_out;

    fused_add_ln<<<NTOK, 256>>>(input, residual, bias, attn_nw, attn_nb);

    // GEMM1: [8192,4096] @ [4096,16384] -> gelu -> g_inter
    gemm_f16<0, HIDDEN, INTER><<<dim3(INTER / 128, NTOK / 128), 256>>>(
        inter_w, inter_b, nullptr);
    // GEMM2: [8192,16384] @ [16384,4096] + res + output_b -> out
    gemm_f16<1, INTER, HIDDEN><<<dim3(HIDDEN / 128, NTOK / 128), 256>>>(
        output_w, output_b, out);
}

// round 14
// speedup vs baseline: 26.1032x; 1.2898x over previous
#include <cuda_runtime.h>
#include <cuda_fp16.h>
#include <math.h>
#include <stdint.h>

#define HIDDEN 4096
#define INTER  16384
#define NTOK   8192
#define EPS    1e-5f

#define SA_ST 40    // halves per A row (32 + 8 pad)  -> 80B row step
#define SB_ST 136   // halves per B row (128 + 8 pad) -> 272B row step

// ---------------- scratch (allocation-free) ----------------
__device__ float g_res[(size_t)NTOK * HIDDEN];      // fp32 residual
__device__ float g_ln [(size_t)NTOK * HIDDEN];      // fp32 LN out
__device__ float g_inter[(size_t)NTOK * INTER];     // fp32 gelu out

// ---------------- helpers ----------------
__device__ __forceinline__ float gelu_tanh(float x) {
    float x3 = x * x * x;
    float t = tanhf(0.7978845608028654f * (x + 0.044715f * x3));
    return 0.5f * x * (1.0f + t);
}
__device__ __forceinline__ uint32_t packh2(float lo, float hi) {
    __half2 h = __floats2half2_rn(lo, hi);
    return *(uint32_t*)&h;
}
__device__ __forceinline__ uint32_t smem_u32(const void* p) {
    uint32_t a;
    asm("{ .reg .u64 t; cvta.to.shared.u64 t, %1; cvt.u32.u64 %0, t; }" : "=r"(a) : "l"(p));
    return a;
}
__device__ __forceinline__ void ldsm_x4(uint32_t r[4], uint32_t addr) {
    asm volatile("ldmatrix.sync.aligned.m8n8.x4.shared.b16 {%0,%1,%2,%3}, [%4];"
                 : "=r"(r[0]), "=r"(r[1]), "=r"(r[2]), "=r"(r[3]) : "r"(addr));
}
__device__ __forceinline__ void ldsm_x4_t(uint32_t r[4], uint32_t addr) {
    asm volatile("ldmatrix.sync.aligned.m8n8.x4.trans.shared.b16 {%0,%1,%2,%3}, [%4];"
                 : "=r"(r[0]), "=r"(r[1]), "=r"(r[2]), "=r"(r[3]) : "r"(addr));
}
__device__ __forceinline__ void mma_f16(float c[4], const uint32_t a[4], const uint32_t b[2]) {
    asm volatile(
        "mma.sync.aligned.m16n8k16.row.col.f32.f16.f16.f32 "
        "{%0,%1,%2,%3}, {%4,%5,%6,%7}, {%8,%9}, {%0,%1,%2,%3};\n"
        : "+f"(c[0]), "+f"(c[1]), "+f"(c[2]), "+f"(c[3])
        : "r"(a[0]), "r"(a[1]), "r"(a[2]), "r"(a[3]),
          "r"(b[0]), "r"(b[1]));
}

// ---------------------------------------------------------------------------
// Kernel 1: res = input + residual + bias (fp32); ln = LN(res)*g+b (fp32)
// ---------------------------------------------------------------------------
__global__ __launch_bounds__(256)
void fused_add_ln(const float* __restrict__ inp,
                  const float* __restrict__ resd,
                  const float* __restrict__ bias,
                  const float* __restrict__ gamma,
                  const float* __restrict__ beta) {
    int row = blockIdx.x;
    int tid = threadIdx.x;
    const float4* ip = (const float4*)(inp  + (size_t)row * HIDDEN);
    const float4* rp = (const float4*)(resd + (size_t)row * HIDDEN);
    const float4* bp = (const float4*)bias;

    float4 v[4];
    float s = 0.f, ss = 0.f;
#pragma unroll
    for (int i = 0; i < 4; i++) {
        int idx = tid + i * 256;
        float4 a = ip[idx], b = rp[idx], c = bp[idx];
        float4 r;
        r.x = a.x + b.x + c.x; r.y = a.y + b.y + c.y;
        r.z = a.z + b.z + c.z; r.w = a.w + b.w + c.w;
        v[i] = r;
        s  += r.x + r.y + r.z + r.w;
        ss += r.x * r.x + r.y * r.y + r.z * r.z + r.w * r.w;
    }
    float4* ro = (float4*)(g_res + (size_t)row * HIDDEN);
#pragma unroll
    for (int i = 0; i < 4; i++) ro[tid + i * 256] = v[i];

    __shared__ float rs[256], rss[256];
    rs[tid] = s; rss[tid] = ss;
    __syncthreads();
    for (int o = 128; o > 0; o >>= 1) {
        if (tid < o) { rs[tid] += rs[tid + o]; rss[tid] += rss[tid + o]; }
        __syncthreads();
    }
    float mu   = rs[0] * (1.0f / HIDDEN);
    float var  = rss[0] * (1.0f / HIDDEN) - mu * mu;
    float rstd = rsqrtf(var + EPS);

    const float4* gp  = (const float4*)gamma;
    const float4* btp = (const float4*)beta;
    float4* lo = (float4*)(g_ln + (size_t)row * HIDDEN);
#pragma unroll
    for (int i = 0; i < 4; i++) {
        int idx = tid + i * 256;
        float4 g = gp[idx], bt = btp[idx], r = v[i];
        float4 o;
        o.x = (r.x - mu) * rstd * g.x + bt.x;
        o.y = (r.y - mu) * rstd * g.y + bt.y;
        o.z = (r.z - mu) * rstd * g.z + bt.z;
        o.w = (r.w - mu) * rstd * g.w + bt.w;
        lo[idx] = o;
    }
}

// ---------------------------------------------------------------------------
// fp16 GEMM, fp16 SMEM + ldmatrix fragments:
// C[M,N] = A[M,K] @ B[K,N] (+ epilogue), fp32 accum.
// Block tile 128x128x32, 8 warps (4Mx2N), warp tile 32x64, m16n8k16.
// fp32->fp16 conversion at STS time; mainloop = 12 ldmatrix + 32 MMA per iter.
// EPI==0: A=g_ln,    out = gelu(c + bias) -> g_inter (fp32)
// EPI==1: A=g_inter, out = c + g_res + bias -> Cout (fp32)
// ---------------------------------------------------------------------------
template <int EPI, int K, int N>
__global__ __launch_bounds__(256, 2)
void gemm_f16(const float* __restrict__ Bw,
              const float* __restrict__ bias,
              float* __restrict__ Cout) {
    __shared__ __half sA[128 * SA_ST];
    __shared__ __half sB[32 * SB_ST];
    const float* __restrict__ A = (EPI == 0) ? g_ln : g_inter;

    int tid = threadIdx.x;
    int warp = tid >> 5, lane = tid & 31;
    int wm = warp & 3;       // M slab 0..3
    int wn = warp >> 2;      // N slab 0..1
    int gID = lane >> 2;     // 0..7
    int tg = lane & 3;       // 0..3

    size_t m0 = (size_t)blockIdx.y * 128;
    size_t n0 = (size_t)blockIdx.x * 128;

    uint32_t sA_base = smem_u32(sA);
    uint32_t sB_base = smem_u32(sB);

    // ldmatrix per-lane base addresses (byte offsets)
    // A (x4, non-trans): row = wm*32 + mi*16 + (lane&15), col = kk + (lane>>4)*8
    uint32_t aAddr = sA_base +
        ((uint32_t)(wm * 32 + (lane & 15)) * SA_ST + ((lane >> 4) * 8)) * 2;
    // B (x4, trans): k-row = kk + (lane&15), n = wn*64 + nj*16 + (lane>>4)*8
    uint32_t bAddr = sB_base +
        ((uint32_t)(lane & 15) * SB_ST + (wn * 64 + (lane >> 4) * 8)) * 2;

    float acc[2][8][4];
#pragma unroll
    for (int mi = 0; mi < 2; mi++)
#pragma unroll
        for (int ni = 0; ni < 8; ni++)
#pragma unroll
            for (int j = 0; j < 4; j++) acc[mi][ni][j] = 0.f;

    const int NK = K / 32;
#pragma unroll 1
    for (int i = 0; i < NK; i++) {
        size_t k0 = (size_t)i * 32;
        // A tile: 128x32 fp32 -> fp16 (4 float4 per thread)
#pragma unroll
        for (int c = 0; c < 4; c++) {
            int f = tid + c * 256;
            int r = f >> 3, c4 = (f & 7) << 2;
            float4 t = *(const float4*)(A + (m0 + r) * K + k0 + c4);
            *(uint2*)(sA + r * SA_ST + c4) =
                make_uint2(packh2(t.x, t.y), packh2(t.z, t.w));
        }
        // B tile: 32x128 fp32 -> fp16
#pragma unroll
        for (int c = 0; c < 4; c++) {
            int f = tid + c * 256;
            int r = f >> 5, c4 = (f & 31) << 2;
            float4 t = *(const float4*)(Bw + (k0 + r) * N + n0 + c4);
            *(uint2*)(sB + r * SB_ST + c4) =
                make_uint2(packh2(t.x, t.y), packh2(t.z, t.w));
        }
        __syncthreads();

#pragma unroll
        for (int ks = 0; ks < 2; ks++) {
            int kk = ks * 16;
            uint32_t a[2][4], b[8][2];
            ldsm_x4(a[0], aAddr + (uint32_t)kk * 2);
            ldsm_x4(a[1], aAddr + (uint32_t)(16 * SA_ST + kk) * 2);
#pragma unroll
            for (int nj = 0; nj < 4; nj++) {
                uint32_t r4[4];
                ldsm_x4_t(r4, bAddr + (uint32_t)(kk * SB_ST + nj * 16) * 2);
                b[nj * 2 + 0][0] = r4[0];
                b[nj * 2 + 0][1] = r4[1];
                b[nj * 2 + 1][0] = r4[2];
                b[nj * 2 + 1][1] = r4[3];
            }
#pragma unroll
            for (int mi = 0; mi < 2; mi++)
#pragma unroll
                for (int ni = 0; ni < 8; ni++)
                    mma_f16(acc[mi][ni], a[mi], b[ni]);
        }
        __syncthreads();
    }

    // ---- epilogue ----
#pragma unroll
    for (int mi = 0; mi < 2; mi++) {
#pragma unroll
        for (int ni = 0; ni < 8; ni++) {
            size_t row0 = m0 + wm * 32 + mi * 16 + gID;
            size_t col = n0 + wn * 64 + ni * 8 + tg * 2;
            float2 b2 = *(const float2*)(bias + col);
#pragma unroll
            for (int h = 0; h < 2; h++) {
                size_t row = row0 + h * 8;
                float x0 = acc[mi][ni][h * 2 + 0] + b2.x;
                float x1 = acc[mi][ni][h * 2 + 1] + b2.y;
                if (EPI == 0) {
                    float2 o;
                    o.x = gelu_tanh(x0);
                    o.y = gelu_tanh(x1);
                    *(float2*)(g_inter + row * INTER + col) = o;
                } else {
                    float2 r2 = *(const float2*)(g_res + row * HIDDEN + col);
                    float2 o;
                    o.x = x0 + r2.x;
                    o.y = x1 + r2.y;
                    *(float2*)(Cout + row * HIDDEN + col) = o;
                }
            }
        }
    }
}

// ---------------------------------------------------------------------------
extern "C" void kernel_launch(void* const* d_in, const int* in_sizes, int n_in,
                              void* d_out, int out_size) {
    const float* input    = (const float*)d_in[0];
    const float* residual = (const float*)d_in[1];
    const float* bias     = (const float*)d_in[3];
    const float* attn_nw  = (const float*)d_in[4];
    const float* attn_nb  = (const float*)d_in[5];
    const float* inter_w  = (const float*)d_in[6];
    const float* inter_b  = (const float*)d_in[7];
    const float* output_w = (const float*)d_in[8];
    const float* output_b = (const float*)d_in[9];
    float* out = (float*)d_out;

    fused_add_ln<<<NTOK, 256>>>(input, residual, bias, attn_nw, attn_nb);

    // GEMM1: [8192,4096] @ [4096,16384] -> gelu -> g_inter
    gemm_f16<0, HIDDEN, INTER><<<dim3(INTER / 128, NTOK / 128), 256>>>(
        inter_w, inter_b, nullptr);
    // GEMM2: [8192,16384] @ [16384,4096] + res + output_b -> out
    gemm_f16<1, INTER, HIDDEN><<<dim3(HIDDEN / 128, NTOK / 128), 256>>>(
        output_w, output_b, out);
}

// round 17
// speedup vs baseline: 39.9337x; 1.5298x over previous
#include <cuda_runtime.h>
#include <cuda_fp16.h>
#include <math.h>
#include <stdint.h>

#define HIDDEN 4096
#define INTER  16384
#define NTOK   8192
#define EPS    1e-5f

#define SA_ST 40    // halves per A row (32 + 8 pad)  -> 80B row step
#define SB_ST 136   // halves per B row (128 + 8 pad) -> 272B row step

// ---------------- scratch (allocation-free) ----------------
__device__ float g_res[(size_t)NTOK * HIDDEN];      // fp32 residual
__device__ float g_ln [(size_t)NTOK * HIDDEN];      // fp32 LN out
__device__ float g_inter[(size_t)NTOK * INTER];     // fp32 gelu out

// ---------------- helpers ----------------
__device__ __forceinline__ float gelu_tanh(float x) {
    float x3 = x * x * x;
    float t = tanhf(0.7978845608028654f * (x + 0.044715f * x3));
    return 0.5f * x * (1.0f + t);
}
__device__ __forceinline__ uint32_t packh2(float lo, float hi) {
    __half2 h = __floats2half2_rn(lo, hi);
    return *(uint32_t*)&h;
}
__device__ __forceinline__ uint32_t smem_u32(const void* p) {
    uint32_t a;
    asm("{ .reg .u64 t; cvta.to.shared.u64 t, %1; cvt.u32.u64 %0, t; }" : "=r"(a) : "l"(p));
    return a;
}
__device__ __forceinline__ void ldsm_x4(uint32_t r[4], uint32_t addr) {
    asm volatile("ldmatrix.sync.aligned.m8n8.x4.shared.b16 {%0,%1,%2,%3}, [%4];"
                 : "=r"(r[0]), "=r"(r[1]), "=r"(r[2]), "=r"(r[3]) : "r"(addr));
}
__device__ __forceinline__ void ldsm_x4_t(uint32_t r[4], uint32_t addr) {
    asm volatile("ldmatrix.sync.aligned.m8n8.x4.trans.shared.b16 {%0,%1,%2,%3}, [%4];"
                 : "=r"(r[0]), "=r"(r[1]), "=r"(r[2]), "=r"(r[3]) : "r"(addr));
}
__device__ __forceinline__ void mma_f16(float c[4], const uint32_t a[4], const uint32_t b[2]) {
    asm volatile(
        "mma.sync.aligned.m16n8k16.row.col.f32.f16.f16.f32 "
        "{%0,%1,%2,%3}, {%4,%5,%6,%7}, {%8,%9}, {%0,%1,%2,%3};\n"
        : "+f"(c[0]), "+f"(c[1]), "+f"(c[2]), "+f"(c[3])
        : "r"(a[0]), "r"(a[1]), "r"(a[2]), "r"(a[3]),
          "r"(b[0]), "r"(b[1]));
}

// ---------------------------------------------------------------------------
// Kernel 1: res = input + residual + bias (fp32); ln = LN(res)*g+b (fp32)
// ---------------------------------------------------------------------------
__global__ __launch_bounds__(256)
void fused_add_ln(const float* __restrict__ inp,
                  const float* __restrict__ resd,
                  const float* __restrict__ bias,
                  const float* __restrict__ gamma,
                  const float* __restrict__ beta) {
    int row = blockIdx.x;
    int tid = threadIdx.x;
    const float4* ip = (const float4*)(inp  + (size_t)row * HIDDEN);
    const float4* rp = (const float4*)(resd + (size_t)row * HIDDEN);
    const float4* bp = (const float4*)bias;

    float4 v[4];
    float s = 0.f, ss = 0.f;
#pragma unroll
    for (int i = 0; i < 4; i++) {
        int idx = tid + i * 256;
        float4 a = ip[idx], b = rp[idx], c = bp[idx];
        float4 r;
        r.x = a.x + b.x + c.x; r.y = a.y + b.y + c.y;
        r.z = a.z + b.z + c.z; r.w = a.w + b.w + c.w;
        v[i] = r;
        s  += r.x + r.y + r.z + r.w;
        ss += r.x * r.x + r.y * r.y + r.z * r.z + r.w * r.w;
    }
    float4* ro = (float4*)(g_res + (size_t)row * HIDDEN);
#pragma unroll
    for (int i = 0; i < 4; i++) ro[tid + i * 256] = v[i];

    __shared__ float rs[256], rss[256];
    rs[tid] = s; rss[tid] = ss;
    __syncthreads();
    for (int o = 128; o > 0; o >>= 1) {
        if (tid < o) { rs[tid] += rs[tid + o]; rss[tid] += rss[tid + o]; }
        __syncthreads();
    }
    float mu   = rs[0] * (1.0f / HIDDEN);
    float var  = rss[0] * (1.0f / HIDDEN) - mu * mu;
    float rstd = rsqrtf(var + EPS);

    const float4* gp  = (const float4*)gamma;
    const float4* btp = (const float4*)beta;
    float4* lo = (float4*)(g_ln + (size_t)row * HIDDEN);
#pragma unroll
    for (int i = 0; i < 4; i++) {
        int idx = tid + i * 256;
        float4 g = gp[idx], bt = btp[idx], r = v[i];
        float4 o;
        o.x = (r.x - mu) * rstd * g.x + bt.x;
        o.y = (r.y - mu) * rstd * g.y + bt.y;
        o.z = (r.z - mu) * rstd * g.z + bt.z;
        o.w = (r.w - mu) * rstd * g.w + bt.w;
        lo[idx] = o;
    }
}

// ---------------------------------------------------------------------------
// fp16 GEMM, fp16 SMEM + ldmatrix + 2-stage pipelined mainloop:
// C[M,N] = A[M,K] @ B[K,N] (+ epilogue), fp32 accum.
// Block tile 128x128x32, 8 warps (4Mx2N), warp tile 32x64, m16n8k16.
// Register-prefetch LDG(i+1) -> compute(i) -> STS(i+1) -> one barrier.
// EPI==0: A=g_ln,    out = gelu(c + bias) -> g_inter (fp32)
// EPI==1: A=g_inter, out = c + g_res + bias -> Cout (fp32)
// ---------------------------------------------------------------------------
template <int EPI, int K, int N>
__global__ __launch_bounds__(256)
void gemm_f16(const float* __restrict__ Bw,
              const float* __restrict__ bias,
              float* __restrict__ Cout) {
    __shared__ __half sA[2][128 * SA_ST];
    __shared__ __half sB[2][32 * SB_ST];
    const float* __restrict__ A = (EPI == 0) ? g_ln : g_inter;

    int tid = threadIdx.x;
    int warp = tid >> 5, lane = tid & 31;
    int wm = warp & 3;       // M slab 0..3
    int wn = warp >> 2;      // N slab 0..1
    int gID = lane >> 2;     // 0..7
    int tg = lane & 3;       // 0..3

    size_t m0 = (size_t)blockIdx.y * 128;
    size_t n0 = (size_t)blockIdx.x * 128;

    // per-thread load coordinates
    int ra = tid >> 3, ca = (tid & 7) << 2;     // A: rows 0..31(+32c), col ca..ca+3
    int rb = tid >> 5, cb = (tid & 31) << 2;    // B: rows 0..7(+8c),  col cb..cb+3

    // ldmatrix per-lane base addresses (byte offsets), stage 0
    uint32_t sA0 = smem_u32(sA);
    uint32_t sB0 = smem_u32(sB);
    const uint32_t A_STAGE = 128 * SA_ST * 2;   // bytes per A stage
    const uint32_t B_STAGE = 32 * SB_ST * 2;    // bytes per B stage
    uint32_t aAddr = sA0 +
        ((uint32_t)(wm * 32 + (lane & 15)) * SA_ST + ((lane >> 4) * 8)) * 2;
    uint32_t bAddr = sB0 +
        ((uint32_t)(lane & 15) * SB_ST + (wn * 64 + (lane >> 4) * 8)) * 2;

    float acc[2][8][4];
#pragma unroll
    for (int mi = 0; mi < 2; mi++)
#pragma unroll
        for (int ni = 0; ni < 8; ni++)
#pragma unroll
            for (int j = 0; j < 4; j++) acc[mi][ni][j] = 0.f;

    const int NK = K / 32;

    // ---- prologue: load tile 0 into stage 0 ----
    {
#pragma unroll
        for (int c = 0; c < 4; c++) {
            int r = ra + c * 32;
            float4 t = *(const float4*)(A + (m0 + r) * K + 0 + ca);
            *(uint2*)(&sA[0][r * SA_ST + ca]) =
                make_uint2(packh2(t.x, t.y), packh2(t.z, t.w));
        }
#pragma unroll
        for (int c = 0; c < 4; c++) {
            int r = rb + c * 8;
            float4 t = *(const float4*)(Bw + (size_t)(0 + r) * N + n0 + cb);
            *(uint2*)(&sB[0][r * SB_ST + cb]) =
                make_uint2(packh2(t.x, t.y), packh2(t.z, t.w));
        }
    }
    __syncthreads();

#pragma unroll 1
    for (int i = 0; i < NK; i++) {
        int cur = i & 1, nxt = cur ^ 1;

        // ---- prefetch tile i+1 into registers (in flight during compute) ----
        float4 pa[4], pb[4];
        if (i + 1 < NK) {
            size_t k1 = (size_t)(i + 1) * 32;
#pragma unroll
            for (int c = 0; c < 4; c++) {
                int r = ra + c * 32;
                pa[c] = *(const float4*)(A + (m0 + r) * K + k1 + ca);
            }
#pragma unroll
            for (int c = 0; c < 4; c++) {
                int r = rb + c * 8;
                pb[c] = *(const float4*)(Bw + (k1 + r) * N + n0 + cb);
            }
        }

        // ---- compute from stage cur ----
        uint32_t aS = aAddr + cur * A_STAGE;
        uint32_t bS = bAddr + cur * B_STAGE;
#pragma unroll
        for (int ks = 0; ks < 2; ks++) {
            int kk = ks * 16;
            uint32_t a[2][4], b[8][2];
            ldsm_x4(a[0], aS + (uint32_t)kk * 2);
            ldsm_x4(a[1], aS + (uint32_t)(16 * SA_ST + kk) * 2);
#pragma unroll
            for (int nj = 0; nj < 4; nj++) {
                uint32_t r4[4];
                ldsm_x4_t(r4, bS + (uint32_t)(kk * SB_ST + nj * 16) * 2);
                b[nj * 2 + 0][0] = r4[0];
                b[nj * 2 + 0][1] = r4[1];
                b[nj * 2 + 1][0] = r4[2];
                b[nj * 2 + 1][1] = r4[3];
            }
#pragma unroll
            for (int mi = 0; mi < 2; mi++)
#pragma unroll
                for (int ni = 0; ni < 8; ni++)
                    mma_f16(acc[mi][ni], a[mi], b[ni]);
        }

        // ---- store prefetched tile into stage nxt; one barrier per iter ----
        if (i + 1 < NK) {
#pragma unroll
            for (int c = 0; c < 4; c++) {
                int r = ra + c * 32;
                *(uint2*)(&sA[nxt][r * SA_ST + ca]) =
                    make_uint2(packh2(pa[c].x, pa[c].y), packh2(pa[c].z, pa[c].w));
            }
#pragma unroll
            for (int c = 0; c < 4; c++) {
                int r = rb + c * 8;
                *(uint2*)(&sB[nxt][r * SB_ST + cb]) =
                    make_uint2(packh2(pb[c].x, pb[c].y), packh2(pb[c].z, pb[c].w));
            }
        }
        __syncthreads();
    }

    // ---- epilogue ----
#pragma unroll
    for (int mi = 0; mi < 2; mi++) {
#pragma unroll
        for (int ni = 0; ni < 8; ni++) {
            size_t row0 = m0 + wm * 32 + mi * 16 + gID;
            size_t col = n0 + wn * 64 + ni * 8 + tg * 2;
            float2 b2 = *(const float2*)(bias + col);
#pragma unroll
            for (int h = 0; h < 2; h++) {
                size_t row = row0 + h * 8;
                float x0 = acc[mi][ni][h * 2 + 0] + b2.x;
                float x1 = acc[mi][ni][h * 2 + 1] + b2.y;
                if (EPI == 0) {
                    float2 o;
                    o.x = gelu_tanh(x0);
                    o.y = gelu_tanh(x1);
                    *(float2*)(g_inter + row * INTER + col) = o;
                } else {
                    float2 r2 = *(const float2*)(g_res + row * HIDDEN + col);
                    float2 o;
                    o.x = x0 + r2.x;
                    o.y = x1 + r2.y;
                    *(float2*)(Cout + row * HIDDEN + col) = o;
                }
            }
        }
    }
}

// ---------------------------------------------------------------------------
extern "C" void kernel_launch(void* const* d_in, const int* in_sizes, int n_in,
                              void* d_out, int out_size) {
    const float* input    = (const float*)d_in[0];
    const float* residual = (const float*)d_in[1];
    const float* bias     = (const float*)d_in[3];
    const float* attn_nw  = (const float*)d_in[4];
    const float* attn_nb  = (const float*)d_in[5];
    const float* inter_w  = (const float*)d_in[6];
    const float* inter_b  = (const float*)d_in[7];
    const float* output_w = (const float*)d_in[8];
    const float* output_b = (const float*)d_in[9];
    float* out = (float*)d_out;

    fused_add_ln<<<NTOK, 256>>>(input, residual, bias, attn_nw, attn_nb);

    // GEMM1: [8192,4096] @ [4096,16384] -> gelu -> g_inter
    gemm_f16<0, HIDDEN, INTER><<<dim3(INTER / 128, NTOK / 128), 256>>>(
        inter_w, inter_b, nullptr);
    // GEMM2: [8192,16384] @ [16384,4096] + res + output_b -> out
    gemm_f16<1, INTER, HIDDEN><<<dim3(HIDDEN / 128, NTOK / 128), 256>>>(
        output_w, output_b, out);
}